// round 8
// baseline (speedup 1.0000x reference)
#include <cuda_runtime.h>

#define BB 64
#define LL 512
#define HH 512
#define NBLK 148

typedef unsigned long long ull;

// Scratch (device globals, zero-initialized at module load; kernel maintains the
// "zero at exit" invariant for g_S/g_UV/g_LV/g_ticket so no zeroing phase).
__device__ __align__(16) float g_S[HH][BB][4];   // packed {ca,cb,da,db}-weighted sums
__device__ __align__(16) float g_UV[HH][BB][2];  // packed {U,V}
__device__ __align__(16) float g_LV[BB][HH];
__device__ __align__(16) float g_usr[HH];
__device__ unsigned g_ticket;

// two-level barrier state
__device__ unsigned g_cnt1[320];          // 10 groups, 128B apart
__device__ unsigned g_cnt2;
__device__ volatile unsigned g_gen;

__device__ __forceinline__ void grid_sync() {
    __syncthreads();
    if (threadIdx.x == 0) {
        unsigned gen = g_gen;
        __threadfence();                                  // release
        unsigned g = blockIdx.x >> 4;                     // 10 groups (last has 4)
        unsigned gs = (g == 9u) ? 4u : 16u;
        if (atomicAdd(&g_cnt1[g * 32], 1u) == gs - 1u) {
            g_cnt1[g * 32] = 0u;
            __threadfence();
            if (atomicAdd(&g_cnt2, 1u) == 9u) {
                g_cnt2 = 0u;
                __threadfence();
                g_gen = gen + 1u;
            } else {
                while (g_gen == gen) {}
            }
        } else {
            while (g_gen == gen) {}
        }
        __threadfence();                                  // acquire
    }
    __syncthreads();
}

// ---- packed fp32x2 helpers -------------------------------------------------
__device__ __forceinline__ ull pack2(float x, float y) {
    ull r; asm("mov.b64 %0, {%1, %2};" : "=l"(r) : "f"(x), "f"(y)); return r;
}
__device__ __forceinline__ ull bcast2(float x) { return pack2(x, x); }
__device__ __forceinline__ float2 unpack2(ull v) {
    float2 r; asm("mov.b64 {%0, %1}, %2;" : "=f"(r.x), "=f"(r.y) : "l"(v)); return r;
}
__device__ __forceinline__ void ffma2(ull& d, ull a, ull b) {
    asm("fma.rn.f32x2 %0, %1, %2, %0;" : "+l"(d) : "l"(a), "l"(b));
}

__global__ void __launch_bounds__(1024, 1) k_fused(
        const float* __restrict__ tdu, const float* __restrict__ tdl,
        const float* __restrict__ ldu, const float* __restrict__ ldl,
        const int*   __restrict__ cur, const int* __restrict__ llen,
        const float* __restrict__ wih, const float* __restrict__ wtu,
        const float* __restrict__ wtl, const float* __restrict__ wsu,
        const float* __restrict__ wsl, const float* __restrict__ h0,
        const float* __restrict__ locw, float* __restrict__ out) {
    __shared__ __align__(16) unsigned char smem_raw[49152];
    const int B = blockIdx.x;
    const int t = threadIdx.x;

    // ============= P1: gather via work-stealing (+ usr_vec on 140..147) =====
    {
        __shared__ __align__(16) float4 s_cf[4][32];
        __shared__ int s_idx[4][32];
        __shared__ int s_p;

        if (B >= 140) {   // usr_vec = Wih @ h0 : 8 blocks x 64 k, 16 lanes/k
            int k    = (B - 140) * 64 + (t >> 4);
            int lane = t & 15;
            float s = 0.f;
            #pragma unroll 8
            for (int h = lane; h < HH; h += 16)
                s += wih[(size_t)k * HH + h] * __ldg(&h0[h]);
            #pragma unroll
            for (int o = 8; o; o >>= 1) s += __shfl_down_sync(0xffffffffu, s, o, 16);
            if (lane == 0) g_usr[k] = s;
        }

        for (;;) {
            __syncthreads();                 // prev iter done with s_p / s_cf
            if (t == 0) s_p = (int)atomicAdd(&g_ticket, 1u);
            __syncthreads();
            int p = s_p;
            if (p >= 256) break;             // 256 tickets x 4 units = 1024 units

            // stage coefficients: threads 0..127 cover 4 units x 32 rows
            if (t < 128) {
                int ws = t >> 5, r = t & 31;
                int u = p * 4 + ws;
                int b = u >> 4, sp = u & 15;
                int len = __ldg(&llen[b]);
                int l = sp + 16 * r;
                if (l < len) {
                    int o = b * LL + l;
                    float tu = tdu[o], tl = tdl[o];
                    float lu = ldu[o], ll = ldl[o];
                    float tden = 1.f / (tu + tl + 1e-9f);
                    float lden = 1.f / (lu + ll + 1e-9f);
                    float a = tu * tden, bb_ = tl * tden;
                    float c = lu * lden, dd  = ll * lden;
                    s_cf[ws][r]  = make_float4(c * a, c * bb_, dd * a, dd * bb_);
                    s_idx[ws][r] = cur[o];
                }
            }
            __syncthreads();

            // compute: 4 units x 256 threads; thread owns h-pair (2*h2, 2*h2+1)
            int which = t >> 8, h2 = t & 255;
            int u = p * 4 + which;
            int b = u >> 4, sp = u & 15;
            int len = __ldg(&llen[b]);
            int cnt = (len > sp) ? ((len - sp + 15) >> 4) : 0;

            const int*    ix  = s_idx[which];
            const float4* cfp = s_cf[which];
            const float*  base = locw + 2 * h2;

            ull a1 = 0, a2 = 0, a3 = 0, a4 = 0;     // packed (h_even, h_odd)
            int r = 0;
            for (; r + 4 <= cnt; r += 4) {
                ull v0 = __ldg(reinterpret_cast<const ull*>(base + (size_t)ix[r]     * HH));
                ull v1 = __ldg(reinterpret_cast<const ull*>(base + (size_t)ix[r + 1] * HH));
                ull v2 = __ldg(reinterpret_cast<const ull*>(base + (size_t)ix[r + 2] * HH));
                ull v3 = __ldg(reinterpret_cast<const ull*>(base + (size_t)ix[r + 3] * HH));
                float4 c0 = cfp[r], c1 = cfp[r + 1], c2 = cfp[r + 2], c3 = cfp[r + 3];
                ffma2(a1, bcast2(c0.x), v0); ffma2(a2, bcast2(c0.y), v0);
                ffma2(a3, bcast2(c0.z), v0); ffma2(a4, bcast2(c0.w), v0);
                ffma2(a1, bcast2(c1.x), v1); ffma2(a2, bcast2(c1.y), v1);
                ffma2(a3, bcast2(c1.z), v1); ffma2(a4, bcast2(c1.w), v1);
                ffma2(a1, bcast2(c2.x), v2); ffma2(a2, bcast2(c2.y), v2);
                ffma2(a3, bcast2(c2.z), v2); ffma2(a4, bcast2(c2.w), v2);
                ffma2(a1, bcast2(c3.x), v3); ffma2(a2, bcast2(c3.y), v3);
                ffma2(a3, bcast2(c3.z), v3); ffma2(a4, bcast2(c3.w), v3);
            }
            for (; r < cnt; ++r) {
                ull v = __ldg(reinterpret_cast<const ull*>(base + (size_t)ix[r] * HH));
                float4 cf = cfp[r];
                ffma2(a1, bcast2(cf.x), v); ffma2(a2, bcast2(cf.y), v);
                ffma2(a3, bcast2(cf.z), v); ffma2(a4, bcast2(cf.w), v);
            }
            if (cnt > 0) {
                float2 e1 = unpack2(a1), e2 = unpack2(a2), e3 = unpack2(a3), e4 = unpack2(a4);
                atomicAdd(reinterpret_cast<float4*>(&g_S[2 * h2][b][0]),
                          make_float4(e1.x, e2.x, e3.x, e4.x));
                atomicAdd(reinterpret_cast<float4*>(&g_S[2 * h2 + 1][b][0]),
                          make_float4(e1.y, e2.y, e3.y, e4.y));
            }
        }
    }
    grid_sync();

    // ============= P2: mm1  U/V[k][b] = sum_h Wt{u,l}[k][h] * S[h][b] =======
    if (B < 128) {
        int kblk = B >> 4, hsplit = B & 15;        // 8 kblk x 64k, 16 hsplit x 32h
        int k0 = kblk * 64, hb = hsplit * 32;
        float* s_t = reinterpret_cast<float*>(smem_raw);           // [32h][4s][64b]
        float* swt = reinterpret_cast<float*>(smem_raw + 32768);   // [2m][64k][32h]
        #pragma unroll
        for (int i = t; i < 2048; i += 1024) {
            int h = i >> 6, b = i & 63;
            float4 v = __ldcg(reinterpret_cast<const float4*>(&g_S[hb + h][b][0]));
            float* p = &s_t[h * 256 + b];
            p[0] = v.x; p[64] = v.y; p[128] = v.z; p[192] = v.w;
        }
        {
            int m = t >> 9, r = (t >> 3) & 63, i4 = t & 7;
            const float* W = m ? wtl : wtu;
            float4 v = __ldg(reinterpret_cast<const float4*>(
                           &W[(size_t)(k0 + r) * HH + hb + i4 * 4]));
            *reinterpret_cast<float4*>(&swt[(m * 64 + r) * 32 + i4 * 4]) = v;
        }
        __syncthreads();
        int w = t >> 5, lane = t & 31;
        int kg = w & 15, hs = w >> 4;              // 16 kgroups x 4k, 2 hsubs x 16h
        int kb = kg * 4;
        ull aU[4] = {0, 0, 0, 0}, aV[4] = {0, 0, 0, 0};   // packed (b0, b0+1)
        for (int hh = 0; hh < 16; ++hh) {
            int h = hs * 16 + hh;
            const float* row = &s_t[h * 256];
            ull s1 = *reinterpret_cast<const ull*>(&row[2 * lane]);
            ull s2 = *reinterpret_cast<const ull*>(&row[64 + 2 * lane]);
            ull s3 = *reinterpret_cast<const ull*>(&row[128 + 2 * lane]);
            ull s4 = *reinterpret_cast<const ull*>(&row[192 + 2 * lane]);
            #pragma unroll
            for (int j = 0; j < 4; ++j) {
                ull wu = bcast2(swt[(kb + j) * 32 + h]);
                ull wl = bcast2(swt[(64 + kb + j) * 32 + h]);
                ffma2(aU[j], wu, s1); ffma2(aU[j], wl, s2);
                ffma2(aV[j], wu, s3); ffma2(aV[j], wl, s4);
            }
        }
        __syncthreads();
        float4* ub = reinterpret_cast<float4*>(smem_raw);   // [64k][32 pairs]
        #pragma unroll
        for (int p = 0; p < 2; ++p) {
            if (hs == p) {
                #pragma unroll
                for (int j = 0; j < 4; ++j) {
                    float2 u = unpack2(aU[j]), v = unpack2(aV[j]);
                    int idx = (kb + j) * 32 + lane;
                    if (p == 0) ub[idx] = make_float4(u.x, v.x, u.y, v.y);
                    else {
                        float4 x = ub[idx];
                        x.x += u.x; x.y += v.x; x.z += u.y; x.w += v.y;
                        ub[idx] = x;
                    }
                }
            }
            __syncthreads();
        }
        float4* dst = reinterpret_cast<float4*>(&g_UV[k0][0][0]);
        atomicAdd(&dst[t],        ub[t]);
        atomicAdd(&dst[t + 1024], ub[t + 1024]);
    } else {
        if (B == 128 && t == 0) g_ticket = 0u;     // safe: after P1 grid_sync
    }
    grid_sync();

    // ============= P3: mm2  LV[b][k] = sum_h Ws{u,l}[k][h]*{U,V}[h][b] ======
    if (B < 128) {
        int kblk = B >> 3, hsplit = B & 7;         // 16 kblk x 32k, 8 hsplit x 64h
        int k0 = kblk * 32, hb = hsplit * 64;
        ull*   uP  = reinterpret_cast<ull*>(smem_raw);             // [64h][32bp]
        ull*   vP  = reinterpret_cast<ull*>(smem_raw + 16384);     // [64h][32bp]
        float* swt = reinterpret_cast<float*>(smem_raw + 32768);   // [2m][32k][64h]
        #pragma unroll
        for (int i = t; i < 2048; i += 1024) {
            int h = i >> 5, bp = i & 31;
            float4 q = __ldcg(reinterpret_cast<const float4*>(&g_UV[hb + h][bp * 2][0]));
            uP[h * 32 + bp] = pack2(q.x, q.z);     // (U_b0, U_b1)
            vP[h * 32 + bp] = pack2(q.y, q.w);     // (V_b0, V_b1)
        }
        {
            int m = t >> 9, r = (t >> 4) & 31, i4 = t & 15;
            const float* W = m ? wsl : wsu;
            float4 v = __ldg(reinterpret_cast<const float4*>(
                           &W[(size_t)(k0 + r) * HH + hb + i4 * 4]));
            *reinterpret_cast<float4*>(&swt[(m * 32 + r) * 64 + i4 * 4]) = v;
        }
        __syncthreads();
        int w = t >> 5, lane = t & 31;
        int kg = w & 7, hs = w >> 3;               // 8 kgroups x 4k, 4 hsubs x 16h
        int kb = kg * 4;
        ull acc[4] = {0, 0, 0, 0};                 // packed (b0, b0+1)
        for (int hh = 0; hh < 16; ++hh) {
            int h = hs * 16 + hh;
            ull up = uP[h * 32 + lane];
            ull vp = vP[h * 32 + lane];
            #pragma unroll
            for (int j = 0; j < 4; ++j) {
                ull wu = bcast2(swt[(kb + j) * 64 + h]);
                ull wl = bcast2(swt[(32 + kb + j) * 64 + h]);
                ffma2(acc[j], wu, up); ffma2(acc[j], wl, vp);
            }
        }
        __syncthreads();
        float* lv = reinterpret_cast<float*>(smem_raw);   // [32k][64b]
        #pragma unroll
        for (int p = 0; p < 4; ++p) {
            if (hs == p) {
                #pragma unroll
                for (int j = 0; j < 4; ++j) {
                    float2 u = unpack2(acc[j]);
                    int r0 = (kb + j) * 64 + 2 * lane;
                    if (p == 0) { lv[r0] = u.x; lv[r0 + 1] = u.y; }
                    else        { lv[r0] += u.x; lv[r0 + 1] += u.y; }
                }
            }
            __syncthreads();
        }
        int b = t & 63, k = (t >> 6) * 2;
        float2 v = make_float2(lv[k * 64 + b], lv[(k + 1) * 64 + b]);
        atomicAdd(reinterpret_cast<float2*>(&g_LV[b][k0 + k]), v);
    } else {
        // idle blocks restore the g_S == 0 invariant for the next replay
        float4 z = make_float4(0.f, 0.f, 0.f, 0.f);
        for (int i = (B - 128) * 1024 + t; i < 32768; i += 20 * 1024)
            reinterpret_cast<float4*>(g_S)[i] = z;
    }
    grid_sync();

    // ============= P4: softmax (+ zero g_LV / g_UV for next replay) =========
    if (B < 64) {
        float* red = reinterpret_cast<float*>(smem_raw);
        int warp = t >> 5, lane = t & 31;
        float x = -1e30f;
        if (t < 512) {
            x = __ldcg(&g_LV[B][t]) + __ldcg(&g_usr[t]);
            g_LV[B][t] = 0.f;                      // restore invariant
        }
        float m = x;
        #pragma unroll
        for (int o = 16; o; o >>= 1) m = fmaxf(m, __shfl_xor_sync(0xffffffffu, m, o));
        if (lane == 0) red[warp] = m;
        __syncthreads();
        if (t == 0) {
            float M = red[0];
            #pragma unroll
            for (int i = 1; i < 32; ++i) M = fmaxf(M, red[i]);
            red[32] = M;
        }
        __syncthreads();
        float M = red[32];
        float e = (t < 512) ? expf(x - M) : 0.f;
        float s = e;
        #pragma unroll
        for (int o = 16; o; o >>= 1) s += __shfl_xor_sync(0xffffffffu, s, o);
        __syncthreads();
        if (lane == 0) red[warp] = s;
        __syncthreads();
        if (t == 0) {
            float S = 0.f;
            #pragma unroll
            for (int i = 0; i < 32; ++i) S += red[i];
            red[33] = S;
        }
        __syncthreads();
        if (t < 512) out[B * HH + t] = e * (1.f / red[33]);
    } else {
        // restore g_UV == 0 invariant
        int idx = (B - 64) * 1024 + t;
        if (idx < 16384)
            reinterpret_cast<float4*>(g_UV)[idx] = make_float4(0.f, 0.f, 0.f, 0.f);
    }
}

// ---------------------------------------------------------------------------
extern "C" void kernel_launch(void* const* d_in, const int* in_sizes, int n_in,
                              void* d_out, int out_size) {
    const float* tdu  = (const float*)d_in[0];
    const float* tdl  = (const float*)d_in[1];
    const float* ldu  = (const float*)d_in[2];
    const float* ldl  = (const float*)d_in[3];
    const int*   cur  = (const int*)  d_in[4];
    const int*   llen = (const int*)  d_in[5];
    const float* wih  = (const float*)d_in[6];
    const float* wtu  = (const float*)d_in[7];
    const float* wtl  = (const float*)d_in[8];
    const float* wsu  = (const float*)d_in[9];
    const float* wsl  = (const float*)d_in[10];
    const float* h0   = (const float*)d_in[11];
    const float* locw = (const float*)d_in[12];
    float* out = (float*)d_out;

    k_fused<<<NBLK, 1024>>>(tdu, tdl, ldu, ldl, cur, llen,
                            wih, wtu, wtl, wsu, wsl, h0, locw, out);
}

// round 9
// speedup vs baseline: 1.0384x; 1.0384x over previous
#include <cuda_runtime.h>

#define BB 64
#define LL 512
#define HH 512
#define NBLK 148

typedef unsigned long long ull;

// Scratch (device globals, zero-initialized at module load; kernel maintains the
// "zero at exit" invariant for g_S/g_UV/g_LV/g_ticket so no zeroing phase).
__device__ __align__(16) float g_S[HH][BB][4];   // packed {ca,cb,da,db}-weighted sums
__device__ __align__(16) float g_UV[HH][BB][2];  // packed {U,V}
__device__ __align__(16) float g_LV[BB][HH];
__device__ __align__(16) float g_usr[HH];
__device__ unsigned g_ticket;

// two-level barrier state
__device__ unsigned g_cnt1[320];          // 10 groups, 128B apart
__device__ unsigned g_cnt2;
__device__ volatile unsigned g_gen;

__device__ __forceinline__ void grid_sync() {
    __syncthreads();
    if (threadIdx.x == 0) {
        unsigned gen = g_gen;
        __threadfence();                                  // release
        unsigned g = blockIdx.x >> 4;                     // 10 groups (last has 4)
        unsigned gs = (g == 9u) ? 4u : 16u;
        if (atomicAdd(&g_cnt1[g * 32], 1u) == gs - 1u) {
            g_cnt1[g * 32] = 0u;
            __threadfence();
            if (atomicAdd(&g_cnt2, 1u) == 9u) {
                g_cnt2 = 0u;
                __threadfence();
                g_gen = gen + 1u;
            } else {
                while (g_gen == gen) {}
            }
        } else {
            while (g_gen == gen) {}
        }
        __threadfence();                                  // acquire
    }
    __syncthreads();
}

// ---- packed fp32x2 helpers -------------------------------------------------
__device__ __forceinline__ ull pack2(float x, float y) {
    ull r; asm("mov.b64 %0, {%1, %2};" : "=l"(r) : "f"(x), "f"(y)); return r;
}
__device__ __forceinline__ ull bcast2(float x) { return pack2(x, x); }
__device__ __forceinline__ float2 unpack2(ull v) {
    float2 r; asm("mov.b64 {%0, %1}, %2;" : "=f"(r.x), "=f"(r.y) : "l"(v)); return r;
}
__device__ __forceinline__ void ffma2(ull& d, ull a, ull b) {
    asm("fma.rn.f32x2 %0, %1, %2, %0;" : "+l"(d) : "l"(a), "l"(b));
}

__global__ void __launch_bounds__(1024, 1) k_fused(
        const float* __restrict__ tdu, const float* __restrict__ tdl,
        const float* __restrict__ ldu, const float* __restrict__ ldl,
        const int*   __restrict__ cur, const int* __restrict__ llen,
        const float* __restrict__ wih, const float* __restrict__ wtu,
        const float* __restrict__ wtl, const float* __restrict__ wsu,
        const float* __restrict__ wsl, const float* __restrict__ h0,
        const float* __restrict__ locw, float* __restrict__ out) {
    __shared__ __align__(16) unsigned char smem_raw[49152];
    const int B = blockIdx.x;
    const int t = threadIdx.x;

    // ============= P1: gather via work-stealing, LDG.128 units ==============
    // 1024 units: u -> b = u & 63, sp = u >> 6 (16 splits). Unit = 128 threads,
    // thread owns h-quad. Ticket = 8 units (8 different b's). 128 tickets.
    {
        __shared__ __align__(16) float4 s_cf[8][32];
        __shared__ int s_idx[8][32];
        __shared__ int s_p;

        if (B >= 140) {   // usr_vec = Wih @ h0 : 8 blocks x 64 k, 16 lanes/k
            int k    = (B - 140) * 64 + (t >> 4);
            int lane = t & 15;
            float s = 0.f;
            #pragma unroll 8
            for (int h = lane; h < HH; h += 16)
                s += wih[(size_t)k * HH + h] * __ldg(&h0[h]);
            #pragma unroll
            for (int o = 8; o; o >>= 1) s += __shfl_down_sync(0xffffffffu, s, o, 16);
            if (lane == 0) g_usr[k] = s;
        }

        for (;;) {
            __syncthreads();                 // prev iter done with s_p / s_cf
            if (t == 0) s_p = (int)atomicAdd(&g_ticket, 1u);
            __syncthreads();
            int p = s_p;
            if (p >= 128) break;             // 128 tickets x 8 units = 1024 units

            // stage coefficients: threads 0..255 cover 8 units x 32 rows
            if (t < 256) {
                int ws = t >> 5, r = t & 31;
                int u = p * 8 + ws;
                int b = u & 63, sp = u >> 6;
                int len = __ldg(&llen[b]);
                int l = sp + 16 * r;
                if (l < len) {
                    int o = b * LL + l;
                    float tu = tdu[o], tl = tdl[o];
                    float lu = ldu[o], ll = ldl[o];
                    float tden = 1.f / (tu + tl + 1e-9f);
                    float lden = 1.f / (lu + ll + 1e-9f);
                    float a = tu * tden, bb_ = tl * tden;
                    float c = lu * lden, dd  = ll * lden;
                    s_cf[ws][r]  = make_float4(c * a, c * bb_, dd * a, dd * bb_);
                    s_idx[ws][r] = cur[o];
                }
            }
            __syncthreads();

            // compute: 8 units x 128 threads; thread owns h-quad at 4*h4
            int which = t >> 7, h4 = t & 127;
            int u = p * 8 + which;
            int b = u & 63, sp = u >> 6;
            int len = __ldg(&llen[b]);
            int cnt = (len > sp) ? ((len - sp + 15) >> 4) : 0;

            const int*    ix  = s_idx[which];
            const float4* cfp = s_cf[which];
            const float*  base = locw + 4 * h4;

            // accumulators: per sum j, lo = (h0,h1), hi = (h2,h3)
            ull aLo[4] = {0, 0, 0, 0}, aHi[4] = {0, 0, 0, 0};
            int r = 0;
            for (; r + 4 <= cnt; r += 4) {
                float4 v0 = __ldg(reinterpret_cast<const float4*>(base + (size_t)ix[r]     * HH));
                float4 v1 = __ldg(reinterpret_cast<const float4*>(base + (size_t)ix[r + 1] * HH));
                float4 v2 = __ldg(reinterpret_cast<const float4*>(base + (size_t)ix[r + 2] * HH));
                float4 v3 = __ldg(reinterpret_cast<const float4*>(base + (size_t)ix[r + 3] * HH));
                {
                    float4 cf = cfp[r];
                    ull lo = pack2(v0.x, v0.y), hi = pack2(v0.z, v0.w);
                    ffma2(aLo[0], bcast2(cf.x), lo); ffma2(aHi[0], bcast2(cf.x), hi);
                    ffma2(aLo[1], bcast2(cf.y), lo); ffma2(aHi[1], bcast2(cf.y), hi);
                    ffma2(aLo[2], bcast2(cf.z), lo); ffma2(aHi[2], bcast2(cf.z), hi);
                    ffma2(aLo[3], bcast2(cf.w), lo); ffma2(aHi[3], bcast2(cf.w), hi);
                }
                {
                    float4 cf = cfp[r + 1];
                    ull lo = pack2(v1.x, v1.y), hi = pack2(v1.z, v1.w);
                    ffma2(aLo[0], bcast2(cf.x), lo); ffma2(aHi[0], bcast2(cf.x), hi);
                    ffma2(aLo[1], bcast2(cf.y), lo); ffma2(aHi[1], bcast2(cf.y), hi);
                    ffma2(aLo[2], bcast2(cf.z), lo); ffma2(aHi[2], bcast2(cf.z), hi);
                    ffma2(aLo[3], bcast2(cf.w), lo); ffma2(aHi[3], bcast2(cf.w), hi);
                }
                {
                    float4 cf = cfp[r + 2];
                    ull lo = pack2(v2.x, v2.y), hi = pack2(v2.z, v2.w);
                    ffma2(aLo[0], bcast2(cf.x), lo); ffma2(aHi[0], bcast2(cf.x), hi);
                    ffma2(aLo[1], bcast2(cf.y), lo); ffma2(aHi[1], bcast2(cf.y), hi);
                    ffma2(aLo[2], bcast2(cf.z), lo); ffma2(aHi[2], bcast2(cf.z), hi);
                    ffma2(aLo[3], bcast2(cf.w), lo); ffma2(aHi[3], bcast2(cf.w), hi);
                }
                {
                    float4 cf = cfp[r + 3];
                    ull lo = pack2(v3.x, v3.y), hi = pack2(v3.z, v3.w);
                    ffma2(aLo[0], bcast2(cf.x), lo); ffma2(aHi[0], bcast2(cf.x), hi);
                    ffma2(aLo[1], bcast2(cf.y), lo); ffma2(aHi[1], bcast2(cf.y), hi);
                    ffma2(aLo[2], bcast2(cf.z), lo); ffma2(aHi[2], bcast2(cf.z), hi);
                    ffma2(aLo[3], bcast2(cf.w), lo); ffma2(aHi[3], bcast2(cf.w), hi);
                }
            }
            for (; r < cnt; ++r) {
                float4 v = __ldg(reinterpret_cast<const float4*>(base + (size_t)ix[r] * HH));
                float4 cf = cfp[r];
                ull lo = pack2(v.x, v.y), hi = pack2(v.z, v.w);
                ffma2(aLo[0], bcast2(cf.x), lo); ffma2(aHi[0], bcast2(cf.x), hi);
                ffma2(aLo[1], bcast2(cf.y), lo); ffma2(aHi[1], bcast2(cf.y), hi);
                ffma2(aLo[2], bcast2(cf.z), lo); ffma2(aHi[2], bcast2(cf.z), hi);
                ffma2(aLo[3], bcast2(cf.w), lo); ffma2(aHi[3], bcast2(cf.w), hi);
            }
            if (cnt > 0) {
                float2 l0 = unpack2(aLo[0]), l1 = unpack2(aLo[1]),
                       l2 = unpack2(aLo[2]), l3 = unpack2(aLo[3]);
                float2 h0_ = unpack2(aHi[0]), h1_ = unpack2(aHi[1]),
                       h2_ = unpack2(aHi[2]), h3_ = unpack2(aHi[3]);
                int H0 = 4 * h4;
                atomicAdd(reinterpret_cast<float4*>(&g_S[H0][b][0]),
                          make_float4(l0.x, l1.x, l2.x, l3.x));
                atomicAdd(reinterpret_cast<float4*>(&g_S[H0 + 1][b][0]),
                          make_float4(l0.y, l1.y, l2.y, l3.y));
                atomicAdd(reinterpret_cast<float4*>(&g_S[H0 + 2][b][0]),
                          make_float4(h0_.x, h1_.x, h2_.x, h3_.x));
                atomicAdd(reinterpret_cast<float4*>(&g_S[H0 + 3][b][0]),
                          make_float4(h0_.y, h1_.y, h2_.y, h3_.y));
            }
        }
    }
    grid_sync();

    // ============= P2: mm1  U/V[k][b] = sum_h Wt{u,l}[k][h] * S[h][b] =======
    if (B < 128) {
        int kblk = B >> 4, hsplit = B & 15;        // 8 kblk x 64k, 16 hsplit x 32h
        int k0 = kblk * 64, hb = hsplit * 32;
        float* s_t = reinterpret_cast<float*>(smem_raw);           // [32h][4s][64b]
        float* swt = reinterpret_cast<float*>(smem_raw + 32768);   // [2m][64k][32h]
        #pragma unroll
        for (int i = t; i < 2048; i += 1024) {
            int h = i >> 6, b = i & 63;
            float4 v = __ldcg(reinterpret_cast<const float4*>(&g_S[hb + h][b][0]));
            float* p = &s_t[h * 256 + b];
            p[0] = v.x; p[64] = v.y; p[128] = v.z; p[192] = v.w;
        }
        {
            int m = t >> 9, r = (t >> 3) & 63, i4 = t & 7;
            const float* W = m ? wtl : wtu;
            float4 v = __ldg(reinterpret_cast<const float4*>(
                           &W[(size_t)(k0 + r) * HH + hb + i4 * 4]));
            *reinterpret_cast<float4*>(&swt[(m * 64 + r) * 32 + i4 * 4]) = v;
        }
        __syncthreads();
        int w = t >> 5, lane = t & 31;
        int kg = w & 15, hs = w >> 4;              // 16 kgroups x 4k, 2 hsubs x 16h
        int kb = kg * 4;
        ull aU[4] = {0, 0, 0, 0}, aV[4] = {0, 0, 0, 0};   // packed (b0, b0+1)
        for (int hh = 0; hh < 16; ++hh) {
            int h = hs * 16 + hh;
            const float* row = &s_t[h * 256];
            ull s1 = *reinterpret_cast<const ull*>(&row[2 * lane]);
            ull s2 = *reinterpret_cast<const ull*>(&row[64 + 2 * lane]);
            ull s3 = *reinterpret_cast<const ull*>(&row[128 + 2 * lane]);
            ull s4 = *reinterpret_cast<const ull*>(&row[192 + 2 * lane]);
            #pragma unroll
            for (int j = 0; j < 4; ++j) {
                ull wu = bcast2(swt[(kb + j) * 32 + h]);
                ull wl = bcast2(swt[(64 + kb + j) * 32 + h]);
                ffma2(aU[j], wu, s1); ffma2(aU[j], wl, s2);
                ffma2(aV[j], wu, s3); ffma2(aV[j], wl, s4);
            }
        }
        __syncthreads();
        float4* ub = reinterpret_cast<float4*>(smem_raw);   // [64k][32 pairs]
        #pragma unroll
        for (int p = 0; p < 2; ++p) {
            if (hs == p) {
                #pragma unroll
                for (int j = 0; j < 4; ++j) {
                    float2 u = unpack2(aU[j]), v = unpack2(aV[j]);
                    int idx = (kb + j) * 32 + lane;
                    if (p == 0) ub[idx] = make_float4(u.x, v.x, u.y, v.y);
                    else {
                        float4 x = ub[idx];
                        x.x += u.x; x.y += v.x; x.z += u.y; x.w += v.y;
                        ub[idx] = x;
                    }
                }
            }
            __syncthreads();
        }
        float4* dst = reinterpret_cast<float4*>(&g_UV[k0][0][0]);
        atomicAdd(&dst[t],        ub[t]);
        atomicAdd(&dst[t + 1024], ub[t + 1024]);
    } else {
        if (B == 128 && t == 0) g_ticket = 0u;     // safe: after P1 grid_sync
    }
    grid_sync();

    // ============= P3: mm2  LV[b][k] = sum_h Ws{u,l}[k][h]*{U,V}[h][b] ======
    if (B < 128) {
        int kblk = B >> 3, hsplit = B & 7;         // 16 kblk x 32k, 8 hsplit x 64h
        int k0 = kblk * 32, hb = hsplit * 64;
        ull*   uP  = reinterpret_cast<ull*>(smem_raw);             // [64h][32bp]
        ull*   vP  = reinterpret_cast<ull*>(smem_raw + 16384);     // [64h][32bp]
        float* swt = reinterpret_cast<float*>(smem_raw + 32768);   // [2m][32k][64h]
        #pragma unroll
        for (int i = t; i < 2048; i += 1024) {
            int h = i >> 5, bp = i & 31;
            float4 q = __ldcg(reinterpret_cast<const float4*>(&g_UV[hb + h][bp * 2][0]));
            uP[h * 32 + bp] = pack2(q.x, q.z);     // (U_b0, U_b1)
            vP[h * 32 + bp] = pack2(q.y, q.w);     // (V_b0, V_b1)
        }
        {
            int m = t >> 9, r = (t >> 4) & 31, i4 = t & 15;
            const float* W = m ? wsl : wsu;
            float4 v = __ldg(reinterpret_cast<const float4*>(
                           &W[(size_t)(k0 + r) * HH + hb + i4 * 4]));
            *reinterpret_cast<float4*>(&swt[(m * 32 + r) * 64 + i4 * 4]) = v;
        }
        __syncthreads();
        int w = t >> 5, lane = t & 31;
        int kg = w & 7, hs = w >> 3;               // 8 kgroups x 4k, 4 hsubs x 16h
        int kb = kg * 4;
        ull acc[4] = {0, 0, 0, 0};                 // packed (b0, b0+1)
        for (int hh = 0; hh < 16; ++hh) {
            int h = hs * 16 + hh;
            ull up = uP[h * 32 + lane];
            ull vp = vP[h * 32 + lane];
            #pragma unroll
            for (int j = 0; j < 4; ++j) {
                ull wu = bcast2(swt[(kb + j) * 64 + h]);
                ull wl = bcast2(swt[(32 + kb + j) * 64 + h]);
                ffma2(acc[j], wu, up); ffma2(acc[j], wl, vp);
            }
        }
        __syncthreads();
        float* lv = reinterpret_cast<float*>(smem_raw);   // [32k][64b]
        #pragma unroll
        for (int p = 0; p < 4; ++p) {
            if (hs == p) {
                #pragma unroll
                for (int j = 0; j < 4; ++j) {
                    float2 u = unpack2(acc[j]);
                    int r0 = (kb + j) * 64 + 2 * lane;
                    if (p == 0) { lv[r0] = u.x; lv[r0 + 1] = u.y; }
                    else        { lv[r0] += u.x; lv[r0 + 1] += u.y; }
                }
            }
            __syncthreads();
        }
        int b = t & 63, k = (t >> 6) * 2;
        float2 v = make_float2(lv[k * 64 + b], lv[(k + 1) * 64 + b]);
        atomicAdd(reinterpret_cast<float2*>(&g_LV[b][k0 + k]), v);
    } else {
        // idle blocks restore the g_S == 0 invariant for the next replay
        float4 z = make_float4(0.f, 0.f, 0.f, 0.f);
        for (int i = (B - 128) * 1024 + t; i < 32768; i += 20 * 1024)
            reinterpret_cast<float4*>(g_S)[i] = z;
    }
    grid_sync();

    // ============= P4: softmax (+ zero g_LV / g_UV for next replay) =========
    if (B < 64) {
        float* red = reinterpret_cast<float*>(smem_raw);
        int warp = t >> 5, lane = t & 31;
        float x = -1e30f;
        if (t < 512) {
            x = __ldcg(&g_LV[B][t]) + __ldcg(&g_usr[t]);
            g_LV[B][t] = 0.f;                      // restore invariant
        }
        float m = x;
        #pragma unroll
        for (int o = 16; o; o >>= 1) m = fmaxf(m, __shfl_xor_sync(0xffffffffu, m, o));
        if (lane == 0) red[warp] = m;
        __syncthreads();
        if (t == 0) {
            float M = red[0];
            #pragma unroll
            for (int i = 1; i < 32; ++i) M = fmaxf(M, red[i]);
            red[32] = M;
        }
        __syncthreads();
        float M = red[32];
        float e = (t < 512) ? expf(x - M) : 0.f;
        float s = e;
        #pragma unroll
        for (int o = 16; o; o >>= 1) s += __shfl_xor_sync(0xffffffffu, s, o);
        __syncthreads();
        if (lane == 0) red[warp] = s;
        __syncthreads();
        if (t == 0) {
            float S = 0.f;
            #pragma unroll
            for (int i = 0; i < 32; ++i) S += red[i];
            red[33] = S;
        }
        __syncthreads();
        if (t < 512) out[B * HH + t] = e * (1.f / red[33]);
    } else {
        // restore g_UV == 0 invariant
        int idx = (B - 64) * 1024 + t;
        if (idx < 16384)
            reinterpret_cast<float4*>(g_UV)[idx] = make_float4(0.f, 0.f, 0.f, 0.f);
    }
}

// ---------------------------------------------------------------------------
extern "C" void kernel_launch(void* const* d_in, const int* in_sizes, int n_in,
                              void* d_out, int out_size) {
    const float* tdu  = (const float*)d_in[0];
    const float* tdl  = (const float*)d_in[1];
    const float* ldu  = (const float*)d_in[2];
    const float* ldl  = (const float*)d_in[3];
    const int*   cur  = (const int*)  d_in[4];
    const int*   llen = (const int*)  d_in[5];
    const float* wih  = (const float*)d_in[6];
    const float* wtu  = (const float*)d_in[7];
    const float* wtl  = (const float*)d_in[8];
    const float* wsu  = (const float*)d_in[9];
    const float* wsl  = (const float*)d_in[10];
    const float* h0   = (const float*)d_in[11];
    const float* locw = (const float*)d_in[12];
    float* out = (float*)d_out;

    k_fused<<<NBLK, 1024>>>(tdu, tdl, ldu, ldl, cur, llen,
                            wih, wtu, wtl, wsu, wsl, h0, locw, out);
}

// round 10
// speedup vs baseline: 1.0473x; 1.0086x over previous
#include <cuda_runtime.h>

#define BB 64
#define LL 512
#define HH 512
#define NBLK 148

typedef unsigned long long ull;

// Scratch (device globals). g_S4 is fully overwritten every launch (no zeroing
// needed). g_UV/g_LV keep the "zero at exit" invariant; g_ticket reset in P2.
__device__ __align__(16) float g_S4[8][HH][BB][4]; // per-split packed sums
__device__ __align__(16) float g_UV[HH][BB][2];    // packed {U,V}
__device__ __align__(16) float g_LV[BB][HH];
__device__ __align__(16) float g_usr[HH];
__device__ unsigned g_ticket;

// two-level barrier state
__device__ unsigned g_cnt1[320];          // 10 groups, 128B apart
__device__ unsigned g_cnt2;
__device__ volatile unsigned g_gen;

__device__ __forceinline__ void grid_sync() {
    __syncthreads();
    if (threadIdx.x == 0) {
        unsigned gen = g_gen;
        __threadfence();                                  // release
        unsigned g = blockIdx.x >> 4;                     // 10 groups (last has 4)
        unsigned gs = (g == 9u) ? 4u : 16u;
        if (atomicAdd(&g_cnt1[g * 32], 1u) == gs - 1u) {
            g_cnt1[g * 32] = 0u;
            __threadfence();
            if (atomicAdd(&g_cnt2, 1u) == 9u) {
                g_cnt2 = 0u;
                __threadfence();
                g_gen = gen + 1u;
            } else {
                while (g_gen == gen) {}
            }
        } else {
            while (g_gen == gen) {}
        }
        __threadfence();                                  // acquire
    }
    __syncthreads();
}

// ---- packed fp32x2 helpers -------------------------------------------------
__device__ __forceinline__ ull pack2(float x, float y) {
    ull r; asm("mov.b64 %0, {%1, %2};" : "=l"(r) : "f"(x), "f"(y)); return r;
}
__device__ __forceinline__ ull bcast2(float x) { return pack2(x, x); }
__device__ __forceinline__ float2 unpack2(ull v) {
    float2 r; asm("mov.b64 {%0, %1}, %2;" : "=f"(r.x), "=f"(r.y) : "l"(v)); return r;
}
__device__ __forceinline__ void ffma2(ull& d, ull a, ull b) {
    asm("fma.rn.f32x2 %0, %1, %2, %0;" : "+l"(d) : "l"(a), "l"(b));
}

__global__ void __launch_bounds__(1024, 1) k_fused(
        const float* __restrict__ tdu, const float* __restrict__ tdl,
        const float* __restrict__ ldu, const float* __restrict__ ldl,
        const int*   __restrict__ cur, const int* __restrict__ llen,
        const float* __restrict__ wih, const float* __restrict__ wtu,
        const float* __restrict__ wtl, const float* __restrict__ wsu,
        const float* __restrict__ wsl, const float* __restrict__ h0,
        const float* __restrict__ locw, float* __restrict__ out) {
    __shared__ __align__(16) unsigned char smem_raw[49152];
    const int B = blockIdx.x;
    const int t = threadIdx.x;

    // ============= P1: gather, atomic-free (per-split output copies) ========
    // 512 units: u -> b = u & 63, sp = u >> 6 (8 splits). Unit = 128 threads,
    // thread owns h-quad. Ticket = 8 units. 64 tickets via work stealing.
    {
        __shared__ __align__(16) float4 s_cf[8][64];
        __shared__ int s_idx[8][64];
        __shared__ int s_p;

        if (B >= 140) {   // usr_vec = Wih @ h0 : 8 blocks x 64 k, 16 lanes/k
            int k    = (B - 140) * 64 + (t >> 4);
            int lane = t & 15;
            float s = 0.f;
            #pragma unroll 8
            for (int h = lane; h < HH; h += 16)
                s += wih[(size_t)k * HH + h] * __ldg(&h0[h]);
            #pragma unroll
            for (int o = 8; o; o >>= 1) s += __shfl_down_sync(0xffffffffu, s, o, 16);
            if (lane == 0) g_usr[k] = s;
        }

        for (;;) {
            __syncthreads();                 // prev iter done with s_p / s_cf
            if (t == 0) s_p = (int)atomicAdd(&g_ticket, 1u);
            __syncthreads();
            int p = s_p;
            if (p >= 64) break;              // 64 tickets x 8 units = 512 units

            // stage coefficients: threads 0..511 cover 8 units x 64 rows
            if (t < 512) {
                int ws = t >> 6, r = t & 63;
                int u = p * 8 + ws;
                int b = u & 63, sp = u >> 6;
                int len = __ldg(&llen[b]);
                int l = sp + 8 * r;
                if (l < len) {
                    int o = b * LL + l;
                    float tu = tdu[o], tl = tdl[o];
                    float lu = ldu[o], ll = ldl[o];
                    float tden = 1.f / (tu + tl + 1e-9f);
                    float lden = 1.f / (lu + ll + 1e-9f);
                    float a = tu * tden, bb_ = tl * tden;
                    float c = lu * lden, dd  = ll * lden;
                    s_cf[ws][r]  = make_float4(c * a, c * bb_, dd * a, dd * bb_);
                    s_idx[ws][r] = cur[o];
                }
            }
            __syncthreads();

            // compute: 8 units x 128 threads; thread owns h-quad at 4*h4
            int which = t >> 7, h4 = t & 127;
            int u = p * 8 + which;
            int b = u & 63, sp = u >> 6;
            int len = __ldg(&llen[b]);
            int cnt = (len > sp) ? ((len - sp + 7) >> 3) : 0;

            const int*    ix  = s_idx[which];
            const float4* cfp = s_cf[which];
            const float*  base = locw + 4 * h4;

            // accumulators: per sum j, lo = (h0,h1), hi = (h2,h3)
            ull aLo[4] = {0, 0, 0, 0}, aHi[4] = {0, 0, 0, 0};
            int r = 0;
            for (; r + 4 <= cnt; r += 4) {
                float4 v0 = __ldg(reinterpret_cast<const float4*>(base + (size_t)ix[r]     * HH));
                float4 v1 = __ldg(reinterpret_cast<const float4*>(base + (size_t)ix[r + 1] * HH));
                float4 v2 = __ldg(reinterpret_cast<const float4*>(base + (size_t)ix[r + 2] * HH));
                float4 v3 = __ldg(reinterpret_cast<const float4*>(base + (size_t)ix[r + 3] * HH));
                {
                    float4 cf = cfp[r];
                    ull lo = pack2(v0.x, v0.y), hi = pack2(v0.z, v0.w);
                    ffma2(aLo[0], bcast2(cf.x), lo); ffma2(aHi[0], bcast2(cf.x), hi);
                    ffma2(aLo[1], bcast2(cf.y), lo); ffma2(aHi[1], bcast2(cf.y), hi);
                    ffma2(aLo[2], bcast2(cf.z), lo); ffma2(aHi[2], bcast2(cf.z), hi);
                    ffma2(aLo[3], bcast2(cf.w), lo); ffma2(aHi[3], bcast2(cf.w), hi);
                }
                {
                    float4 cf = cfp[r + 1];
                    ull lo = pack2(v1.x, v1.y), hi = pack2(v1.z, v1.w);
                    ffma2(aLo[0], bcast2(cf.x), lo); ffma2(aHi[0], bcast2(cf.x), hi);
                    ffma2(aLo[1], bcast2(cf.y), lo); ffma2(aHi[1], bcast2(cf.y), hi);
                    ffma2(aLo[2], bcast2(cf.z), lo); ffma2(aHi[2], bcast2(cf.z), hi);
                    ffma2(aLo[3], bcast2(cf.w), lo); ffma2(aHi[3], bcast2(cf.w), hi);
                }
                {
                    float4 cf = cfp[r + 2];
                    ull lo = pack2(v2.x, v2.y), hi = pack2(v2.z, v2.w);
                    ffma2(aLo[0], bcast2(cf.x), lo); ffma2(aHi[0], bcast2(cf.x), hi);
                    ffma2(aLo[1], bcast2(cf.y), lo); ffma2(aHi[1], bcast2(cf.y), hi);
                    ffma2(aLo[2], bcast2(cf.z), lo); ffma2(aHi[2], bcast2(cf.z), hi);
                    ffma2(aLo[3], bcast2(cf.w), lo); ffma2(aHi[3], bcast2(cf.w), hi);
                }
                {
                    float4 cf = cfp[r + 3];
                    ull lo = pack2(v3.x, v3.y), hi = pack2(v3.z, v3.w);
                    ffma2(aLo[0], bcast2(cf.x), lo); ffma2(aHi[0], bcast2(cf.x), hi);
                    ffma2(aLo[1], bcast2(cf.y), lo); ffma2(aHi[1], bcast2(cf.y), hi);
                    ffma2(aLo[2], bcast2(cf.z), lo); ffma2(aHi[2], bcast2(cf.z), hi);
                    ffma2(aLo[3], bcast2(cf.w), lo); ffma2(aHi[3], bcast2(cf.w), hi);
                }
            }
            for (; r < cnt; ++r) {
                float4 v = __ldg(reinterpret_cast<const float4*>(base + (size_t)ix[r] * HH));
                float4 cf = cfp[r];
                ull lo = pack2(v.x, v.y), hi = pack2(v.z, v.w);
                ffma2(aLo[0], bcast2(cf.x), lo); ffma2(aHi[0], bcast2(cf.x), hi);
                ffma2(aLo[1], bcast2(cf.y), lo); ffma2(aHi[1], bcast2(cf.y), hi);
                ffma2(aLo[2], bcast2(cf.z), lo); ffma2(aHi[2], bcast2(cf.z), hi);
                ffma2(aLo[3], bcast2(cf.w), lo); ffma2(aHi[3], bcast2(cf.w), hi);
            }
            // unconditional plain stores (zeros when cnt==0) — no atomics
            {
                float2 l0 = unpack2(aLo[0]), l1 = unpack2(aLo[1]),
                       l2 = unpack2(aLo[2]), l3 = unpack2(aLo[3]);
                float2 h0_ = unpack2(aHi[0]), h1_ = unpack2(aHi[1]),
                       h2_ = unpack2(aHi[2]), h3_ = unpack2(aHi[3]);
                int H0 = 4 * h4;
                *reinterpret_cast<float4*>(&g_S4[sp][H0][b][0]) =
                    make_float4(l0.x, l1.x, l2.x, l3.x);
                *reinterpret_cast<float4*>(&g_S4[sp][H0 + 1][b][0]) =
                    make_float4(l0.y, l1.y, l2.y, l3.y);
                *reinterpret_cast<float4*>(&g_S4[sp][H0 + 2][b][0]) =
                    make_float4(h0_.x, h1_.x, h2_.x, h3_.x);
                *reinterpret_cast<float4*>(&g_S4[sp][H0 + 3][b][0]) =
                    make_float4(h0_.y, h1_.y, h2_.y, h3_.y);
            }
        }
    }
    grid_sync();

    // ============= P2: mm1  U/V[k][b] = sum_h Wt{u,l}[k][h] * S[h][b] =======
    if (B < 128) {
        int kblk = B >> 4, hsplit = B & 15;        // 8 kblk x 64k, 16 hsplit x 32h
        int k0 = kblk * 64, hb = hsplit * 32;
        float* s_t = reinterpret_cast<float*>(smem_raw);           // [32h][4s][64b]
        float* swt = reinterpret_cast<float*>(smem_raw + 32768);   // [2m][64k][32h]
        #pragma unroll
        for (int i = t; i < 2048; i += 1024) {
            int h = i >> 6, b = i & 63;
            float4 a0 = __ldcg(reinterpret_cast<const float4*>(&g_S4[0][hb + h][b][0]));
            float4 a1 = __ldcg(reinterpret_cast<const float4*>(&g_S4[1][hb + h][b][0]));
            float4 a2 = __ldcg(reinterpret_cast<const float4*>(&g_S4[2][hb + h][b][0]));
            float4 a3 = __ldcg(reinterpret_cast<const float4*>(&g_S4[3][hb + h][b][0]));
            float4 a4 = __ldcg(reinterpret_cast<const float4*>(&g_S4[4][hb + h][b][0]));
            float4 a5 = __ldcg(reinterpret_cast<const float4*>(&g_S4[5][hb + h][b][0]));
            float4 a6 = __ldcg(reinterpret_cast<const float4*>(&g_S4[6][hb + h][b][0]));
            float4 a7 = __ldcg(reinterpret_cast<const float4*>(&g_S4[7][hb + h][b][0]));
            float sx = a0.x + a1.x + a2.x + a3.x + a4.x + a5.x + a6.x + a7.x;
            float sy = a0.y + a1.y + a2.y + a3.y + a4.y + a5.y + a6.y + a7.y;
            float sz = a0.z + a1.z + a2.z + a3.z + a4.z + a5.z + a6.z + a7.z;
            float sw = a0.w + a1.w + a2.w + a3.w + a4.w + a5.w + a6.w + a7.w;
            float* p = &s_t[h * 256 + b];
            p[0] = sx; p[64] = sy; p[128] = sz; p[192] = sw;
        }
        {
            int m = t >> 9, r = (t >> 3) & 63, i4 = t & 7;
            const float* W = m ? wtl : wtu;
            float4 v = __ldg(reinterpret_cast<const float4*>(
                           &W[(size_t)(k0 + r) * HH + hb + i4 * 4]));
            *reinterpret_cast<float4*>(&swt[(m * 64 + r) * 32 + i4 * 4]) = v;
        }
        __syncthreads();
        int w = t >> 5, lane = t & 31;
        int kg = w & 15, hs = w >> 4;              // 16 kgroups x 4k, 2 hsubs x 16h
        int kb = kg * 4;
        ull aU[4] = {0, 0, 0, 0}, aV[4] = {0, 0, 0, 0};   // packed (b0, b0+1)
        for (int hh = 0; hh < 16; ++hh) {
            int h = hs * 16 + hh;
            const float* row = &s_t[h * 256];
            ull s1 = *reinterpret_cast<const ull*>(&row[2 * lane]);
            ull s2 = *reinterpret_cast<const ull*>(&row[64 + 2 * lane]);
            ull s3 = *reinterpret_cast<const ull*>(&row[128 + 2 * lane]);
            ull s4 = *reinterpret_cast<const ull*>(&row[192 + 2 * lane]);
            #pragma unroll
            for (int j = 0; j < 4; ++j) {
                ull wu = bcast2(swt[(kb + j) * 32 + h]);
                ull wl = bcast2(swt[(64 + kb + j) * 32 + h]);
                ffma2(aU[j], wu, s1); ffma2(aU[j], wl, s2);
                ffma2(aV[j], wu, s3); ffma2(aV[j], wl, s4);
            }
        }
        __syncthreads();
        float4* ub = reinterpret_cast<float4*>(smem_raw);   // [64k][32 pairs]
        #pragma unroll
        for (int p = 0; p < 2; ++p) {
            if (hs == p) {
                #pragma unroll
                for (int j = 0; j < 4; ++j) {
                    float2 u = unpack2(aU[j]), v = unpack2(aV[j]);
                    int idx = (kb + j) * 32 + lane;
                    if (p == 0) ub[idx] = make_float4(u.x, v.x, u.y, v.y);
                    else {
                        float4 x = ub[idx];
                        x.x += u.x; x.y += v.x; x.z += u.y; x.w += v.y;
                        ub[idx] = x;
                    }
                }
            }
            __syncthreads();
        }
        float4* dst = reinterpret_cast<float4*>(&g_UV[k0][0][0]);
        atomicAdd(&dst[t],        ub[t]);
        atomicAdd(&dst[t + 1024], ub[t + 1024]);
    } else {
        if (B == 128 && t == 0) g_ticket = 0u;     // safe: after P1 grid_sync
    }
    grid_sync();

    // ============= P3: mm2  LV[b][k] = sum_h Ws{u,l}[k][h]*{U,V}[h][b] ======
    if (B < 128) {
        int kblk = B >> 3, hsplit = B & 7;         // 16 kblk x 32k, 8 hsplit x 64h
        int k0 = kblk * 32, hb = hsplit * 64;
        ull*   uP  = reinterpret_cast<ull*>(smem_raw);             // [64h][32bp]
        ull*   vP  = reinterpret_cast<ull*>(smem_raw + 16384);     // [64h][32bp]
        float* swt = reinterpret_cast<float*>(smem_raw + 32768);   // [2m][32k][64h]
        #pragma unroll
        for (int i = t; i < 2048; i += 1024) {
            int h = i >> 5, bp = i & 31;
            float4 q = __ldcg(reinterpret_cast<const float4*>(&g_UV[hb + h][bp * 2][0]));
            uP[h * 32 + bp] = pack2(q.x, q.z);     // (U_b0, U_b1)
            vP[h * 32 + bp] = pack2(q.y, q.w);     // (V_b0, V_b1)
        }
        {
            int m = t >> 9, r = (t >> 4) & 31, i4 = t & 15;
            const float* W = m ? wsl : wsu;
            float4 v = __ldg(reinterpret_cast<const float4*>(
                           &W[(size_t)(k0 + r) * HH + hb + i4 * 4]));
            *reinterpret_cast<float4*>(&swt[(m * 32 + r) * 64 + i4 * 4]) = v;
        }
        __syncthreads();
        int w = t >> 5, lane = t & 31;
        int kg = w & 7, hs = w >> 3;               // 8 kgroups x 4k, 4 hsubs x 16h
        int kb = kg * 4;
        ull acc[4] = {0, 0, 0, 0};                 // packed (b0, b0+1)
        for (int hh = 0; hh < 16; ++hh) {
            int h = hs * 16 + hh;
            ull up = uP[h * 32 + lane];
            ull vp = vP[h * 32 + lane];
            #pragma unroll
            for (int j = 0; j < 4; ++j) {
                ull wu = bcast2(swt[(kb + j) * 64 + h]);
                ull wl = bcast2(swt[(32 + kb + j) * 64 + h]);
                ffma2(acc[j], wu, up); ffma2(acc[j], wl, vp);
            }
        }
        __syncthreads();
        float* lv = reinterpret_cast<float*>(smem_raw);   // [32k][64b]
        #pragma unroll
        for (int p = 0; p < 4; ++p) {
            if (hs == p) {
                #pragma unroll
                for (int j = 0; j < 4; ++j) {
                    float2 u = unpack2(acc[j]);
                    int r0 = (kb + j) * 64 + 2 * lane;
                    if (p == 0) { lv[r0] = u.x; lv[r0 + 1] = u.y; }
                    else        { lv[r0] += u.x; lv[r0 + 1] += u.y; }
                }
            }
            __syncthreads();
        }
        int b = t & 63, k = (t >> 6) * 2;
        float2 v = make_float2(lv[k * 64 + b], lv[(k + 1) * 64 + b]);
        atomicAdd(reinterpret_cast<float2*>(&g_LV[b][k0 + k]), v);
    }
    grid_sync();

    // ============= P4: softmax (+ zero g_LV / g_UV for next replay) =========
    if (B < 64) {
        float* red = reinterpret_cast<float*>(smem_raw);
        int warp = t >> 5, lane = t & 31;
        float x = -1e30f;
        if (t < 512) {
            x = __ldcg(&g_LV[B][t]) + __ldcg(&g_usr[t]);
            g_LV[B][t] = 0.f;                      // restore invariant
        }
        float m = x;
        #pragma unroll
        for (int o = 16; o; o >>= 1) m = fmaxf(m, __shfl_xor_sync(0xffffffffu, m, o));
        if (lane == 0) red[warp] = m;
        __syncthreads();
        if (t == 0) {
            float M = red[0];
            #pragma unroll
            for (int i = 1; i < 32; ++i) M = fmaxf(M, red[i]);
            red[32] = M;
        }
        __syncthreads();
        float M = red[32];
        float e = (t < 512) ? expf(x - M) : 0.f;
        float s = e;
        #pragma unroll
        for (int o = 16; o; o >>= 1) s += __shfl_xor_sync(0xffffffffu, s, o);
        __syncthreads();
        if (lane == 0) red[warp] = s;
        __syncthreads();
        if (t == 0) {
            float S = 0.f;
            #pragma unroll
            for (int i = 0; i < 32; ++i) S += red[i];
            red[33] = S;
        }
        __syncthreads();
        if (t < 512) out[B * HH + t] = e * (1.f / red[33]);
    } else {
        // restore g_UV == 0 invariant
        int idx = (B - 64) * 1024 + t;
        if (idx < 16384)
            reinterpret_cast<float4*>(g_UV)[idx] = make_float4(0.f, 0.f, 0.f, 0.f);
    }
}

// ---------------------------------------------------------------------------
extern "C" void kernel_launch(void* const* d_in, const int* in_sizes, int n_in,
                              void* d_out, int out_size) {
    const float* tdu  = (const float*)d_in[0];
    const float* tdl  = (const float*)d_in[1];
    const float* ldu  = (const float*)d_in[2];
    const float* ldl  = (const float*)d_in[3];
    const int*   cur  = (const int*)  d_in[4];
    const int*   llen = (const int*)  d_in[5];
    const float* wih  = (const float*)d_in[6];
    const float* wtu  = (const float*)d_in[7];
    const float* wtl  = (const float*)d_in[8];
    const float* wsu  = (const float*)d_in[9];
    const float* wsl  = (const float*)d_in[10];
    const float* h0   = (const float*)d_in[11];
    const float* locw = (const float*)d_in[12];
    float* out = (float*)d_out;

    k_fused<<<NBLK, 1024>>>(tdu, tdl, ldu, ldl, cur, llen,
                            wih, wtu, wtl, wsu, wsl, h0, locw, out);
}